// round 3
// baseline (speedup 1.0000x reference)
#include <cuda_runtime.h>
#include <cstdint>

#define Bc 2
#define Nc 4096
#define Tc 512

// ---------------- scratch (static device globals; no allocation) ----------------
__device__ float g_s2c[Bc * Tc * 128];                 // s_to_c
__device__ int   g_tok[Bc * Nc];                       // token index per atom
__device__ float g_cq[Bc * Nc * 16];                   // relu(c) @ W_cq.T
__device__ float g_ck[Bc * Nc * 16];                   // relu(c) @ W_ck.T
__device__ float g_z2p[(size_t)Bc * Tc * Tc * 16];     // layernorm(z) @ W_z2p.T  (33.5 MB)
__device__ float g_WfeatT[389 * 128];
__device__ float g_Ws2cT[384 * 128];
__device__ float g_gw[16 * 128];                       // W_z2p * ln_z_g (folded)
__device__ float g_gsum[16];
__device__ float g_bw[16];

// ---------------- f32x2 helpers ----------------
__device__ __forceinline__ unsigned long long pack2(float a, float b) {
    unsigned long long r;
    asm("mov.b64 %0, {%1,%2};" : "=l"(r) : "f"(a), "f"(b));
    return r;
}
__device__ __forceinline__ void fma2(unsigned long long& acc, unsigned long long a, unsigned long long b) {
    asm("fma.rn.f32x2 %0, %1, %2, %0;" : "+l"(acc) : "l"(a), "l"(b));
}
__device__ __forceinline__ float lo32(unsigned long long v) { return __uint_as_float((unsigned)(v & 0xffffffffu)); }
__device__ __forceinline__ float hi32(unsigned long long v) { return __uint_as_float((unsigned)(v >> 32)); }

// ---------------- prep: transposes + layernorm fold for z ----------------
__global__ void prep_kernel(const float* __restrict__ W_feat, const float* __restrict__ W_s2c,
                            const float* __restrict__ W_z2p, const float* __restrict__ ln_z_g,
                            const float* __restrict__ ln_z_b) {
    int t = blockIdx.x * blockDim.x + threadIdx.x;
    int nt = gridDim.x * blockDim.x;
    for (int i = t; i < 389 * 128; i += nt) {
        int ch = i / 389, f = i % 389;
        g_WfeatT[f * 128 + ch] = W_feat[i];
    }
    for (int i = t; i < 384 * 128; i += nt) {
        int ch = i / 384, f = i % 384;
        g_Ws2cT[f * 128 + ch] = W_s2c[i];
    }
    for (int i = t; i < 16 * 128; i += nt) {
        int f = i & 127;
        g_gw[i] = W_z2p[i] * ln_z_g[f];
    }
    if (t < 16) {
        float gs = 0.f, bw = 0.f;
        for (int f = 0; f < 128; f++) {
            gs += W_z2p[t * 128 + f] * ln_z_g[f];
            bw += W_z2p[t * 128 + f] * ln_z_b[f];
        }
        g_gsum[t] = gs;
        g_bw[t] = bw;
    }
}

// ---------------- token index extraction (one-hot argmax), warp per atom ----------------
__global__ void tok_kernel(const float* __restrict__ a2t) {
    int warp = (blockIdx.x * blockDim.x + threadIdx.x) >> 5;
    int lane = threadIdx.x & 31;
    if (warp >= Bc * Nc) return;
    const float* row = a2t + (size_t)warp * Tc;
    int idx = 0;
    for (int i = lane; i < Tc; i += 32)
        if (row[i] > 0.5f) idx = i;
#pragma unroll
    for (int o = 16; o; o >>= 1) idx = max(idx, __shfl_xor_sync(0xffffffffu, idx, o));
    if (lane == 0) g_tok[warp] = idx;
}

// ---------------- s_to_c: layernorm(s_trunk) @ W_s2c.T  (block per row, 128 threads) ----------------
__global__ void s2c_kernel(const float* __restrict__ s_trunk, const float* __restrict__ g,
                           const float* __restrict__ bta) {
    __shared__ __align__(16) float xs[384];
    __shared__ float red[8];
    int row = blockIdx.x;
    int tid = threadIdx.x;
    const float* x = s_trunk + (size_t)row * 384;
    float v0 = x[tid], v1 = x[tid + 128], v2 = x[tid + 256];
    float s = v0 + v1 + v2, s2 = v0 * v0 + v1 * v1 + v2 * v2;
#pragma unroll
    for (int o = 16; o; o >>= 1) {
        s += __shfl_xor_sync(0xffffffffu, s, o);
        s2 += __shfl_xor_sync(0xffffffffu, s2, o);
    }
    if ((tid & 31) == 0) { red[tid >> 5] = s; red[4 + (tid >> 5)] = s2; }
    __syncthreads();
    s = red[0] + red[1] + red[2] + red[3];
    s2 = red[4] + red[5] + red[6] + red[7];
    float mu = s * (1.f / 384.f);
    float var = s2 * (1.f / 384.f) - mu * mu;
    float rs = rsqrtf(var + 1e-5f);
    xs[tid]       = (v0 - mu) * rs * g[tid]       + bta[tid];
    xs[tid + 128] = (v1 - mu) * rs * g[tid + 128] + bta[tid + 128];
    xs[tid + 256] = (v2 - mu) * rs * g[tid + 256] + bta[tid + 256];
    __syncthreads();
    float acc = 0.f;
#pragma unroll 4
    for (int f = 0; f < 384; f++) acc += xs[f] * g_Ws2cT[f * 128 + tid];
    g_s2c[(size_t)row * 128 + tid] = acc;
}

// ---------------- c embedding + cq/ck heads (16 atoms per block, 128 threads) ----------------
__global__ void c_kernel(const float* __restrict__ ref_pos, const float* __restrict__ ref_charge,
                         const float* __restrict__ amask, const float* __restrict__ elem,
                         const float* __restrict__ chars,
                         const float* __restrict__ W_cq, const float* __restrict__ W_ck) {
    __shared__ __align__(16) float fs[16 * 389];       // feats, later reused as relu(c) [16][128]
    __shared__ __align__(16) float wcs[2 * 16 * 129];  // padded W_cq / W_ck
    __shared__ int ts[16];
    int tid = threadIdx.x;
    int abase = blockIdx.x * 16;

    for (int idx = tid; idx < 2 * 16 * 128; idx += 128) {
        int which = idx >> 11;
        int i = (idx >> 7) & 15;
        int ch = idx & 127;
        wcs[which * 16 * 129 + i * 129 + ch] = which ? W_ck[i * 128 + ch] : W_cq[i * 128 + ch];
    }
    for (int a = 0; a < 16; a++) {
        int atom = abase + a;
        float* f = fs + a * 389;
        if (tid < 3) f[tid] = ref_pos[atom * 3 + tid];
        if (tid == 3) f[3] = ref_charge[atom];
        if (tid == 4) f[4] = amask[atom];
        f[5 + tid]   = elem[(size_t)atom * 128 + tid];
        f[133 + tid] = chars[(size_t)atom * 256 + tid];
        f[261 + tid] = chars[(size_t)atom * 256 + 128 + tid];
    }
    if (tid < 16) ts[tid] = g_tok[abase + tid];
    __syncthreads();

    float acc[16];
#pragma unroll
    for (int a = 0; a < 16; a++) acc[a] = 0.f;
#pragma unroll 2
    for (int fi = 0; fi < 389; fi++) {
        float w = g_WfeatT[fi * 128 + tid];
#pragma unroll
        for (int a = 0; a < 16; a++) acc[a] += fs[a * 389 + fi] * w;
    }
    int bb = abase / Nc;
    __syncthreads();                 // done reading fs
    float* cs = fs;                  // reuse smem: relu(c), [16][128]
#pragma unroll
    for (int a = 0; a < 16; a++) {
        float cv = acc[a] + g_s2c[((size_t)(bb * Tc + ts[a])) * 128 + tid];
        cs[a * 128 + tid] = fmaxf(cv, 0.f);
    }
    __syncthreads();

    int i = tid & 15;
    int which = (tid >> 4) & 1;
    int a0 = tid >> 5;
    const float* Wrow = wcs + which * 16 * 129 + i * 129;
    float* dst = which ? g_ck : g_cq;
    for (int a = a0; a < 16; a += 4) {
        float sv = 0.f;
        const float* crow = cs + a * 128;
#pragma unroll 16
        for (int ch = 0; ch < 128; ch++) sv += crow[ch] * Wrow[ch];
        dst[(size_t)(abase + a) * 16 + i] = sv;
    }
}

// ---------------- z_to_p: layernorm(z)@W_z2p.T, 64 rows per block, f32x2 dot ----------------
__global__ void z2p_kernel(const float* __restrict__ z) {
    __shared__ __align__(16) float xs[64 * 132];
    __shared__ __align__(16) float gws[16 * 130];
    __shared__ float mus[64], rss[64], gsum_s[16], bw_s[16];
    int tid = threadIdx.x;
    size_t rowbase = (size_t)blockIdx.x * 64;

    for (int i = tid; i < 2048; i += 256)
        gws[(i >> 7) * 130 + (i & 127)] = g_gw[i];
    if (tid < 16) { gsum_s[tid] = g_gsum[tid]; bw_s[tid] = g_bw[tid]; }

    {   // coalesced load + per-row mean/var (4 threads per row)
        int r = tid >> 2, j = tid & 3;
        const float4* src = (const float4*)(z + (rowbase + (size_t)r) * 128) + j * 8;
        float4* dst = (float4*)(xs + r * 132) + j * 8;
        float s = 0.f, s2 = 0.f;
#pragma unroll
        for (int q = 0; q < 8; q++) {
            float4 t = src[q];
            dst[q] = t;
            s += (t.x + t.y) + (t.z + t.w);
            s2 += t.x * t.x + t.y * t.y + t.z * t.z + t.w * t.w;
        }
        s  += __shfl_xor_sync(0xffffffffu, s, 1);
        s2 += __shfl_xor_sync(0xffffffffu, s2, 1);
        s  += __shfl_xor_sync(0xffffffffu, s, 2);
        s2 += __shfl_xor_sync(0xffffffffu, s2, 2);
        if (j == 0) {
            float mu = s * (1.f / 128.f);
            float var = s2 * (1.f / 128.f) - mu * mu;
            mus[r] = mu;
            rss[r] = rsqrtf(var + 1e-5f);
        }
    }
    __syncthreads();

    int ch = tid & 15, rb = tid >> 4;   // 16 ch x 16 row-quads
    const unsigned long long* wp = (const unsigned long long*)(gws + ch * 130);
    const unsigned long long* x0 = (const unsigned long long*)(xs + (rb * 4 + 0) * 132);
    const unsigned long long* x1 = (const unsigned long long*)(xs + (rb * 4 + 1) * 132);
    const unsigned long long* x2 = (const unsigned long long*)(xs + (rb * 4 + 2) * 132);
    const unsigned long long* x3 = (const unsigned long long*)(xs + (rb * 4 + 3) * 132);
    unsigned long long a0 = 0, a1 = 0, a2 = 0, a3 = 0;
#pragma unroll 16
    for (int f2 = 0; f2 < 64; f2++) {
        unsigned long long w = wp[f2];
        fma2(a0, x0[f2], w);
        fma2(a1, x1[f2], w);
        fma2(a2, x2[f2], w);
        fma2(a3, x3[f2], w);
    }
    float gs = gsum_s[ch], bw = bw_s[ch];
    float dots[4] = { lo32(a0) + hi32(a0), lo32(a1) + hi32(a1),
                      lo32(a2) + hi32(a2), lo32(a3) + hi32(a3) };
#pragma unroll
    for (int i = 0; i < 4; i++) {
        int r = rb * 4 + i;
        g_z2p[(rowbase + (size_t)r) * 16 + ch] = rss[r] * (dots[i] - mus[r] * gs) + bw;
    }
}

// ---------------- main: per-position assembly + MLP (thread per (b,kk,ww,hh)) ----------------
__global__ void main_kernel(const float* __restrict__ ref_pos, const float* __restrict__ amask,
                            const int* __restrict__ uid,
                            const float* __restrict__ W_pos, const float* __restrict__ W_dist,
                            const float* __restrict__ W_maskp,
                            const float* __restrict__ W_m1, const float* __restrict__ W_m2,
                            const float* __restrict__ W_m3,
                            float* __restrict__ out) {
    __shared__ __align__(16) float wm[3 * 256];
    __shared__ float wpos[48], wdist[16], wmk[16];
    int tid = threadIdx.x;
    wm[tid] = W_m1[tid];
    wm[256 + tid] = W_m2[tid];
    wm[512 + tid] = W_m3[tid];
    if (tid < 48) wpos[tid] = W_pos[tid];
    if (tid < 16) { wdist[tid] = W_dist[tid]; wmk[tid] = W_maskp[tid]; }
    __syncthreads();

    int gidx = blockIdx.x * 256 + tid;
    int hh = gidx & 127;
    int ww = (gidx >> 7) & 31;
    int kk = (gidx >> 12) & 127;
    int b  = gidx >> 19;
    int q = kk * 32 + ww;
    int key = kk * 32 + hh - 48;
    bool inr = (unsigned)key < (unsigned)Nc;
    int bq = b * Nc + q;
    int bk = b * Nc + (inr ? key : 0);

    float mq = amask[bq];
    float mk = inr ? amask[bk] : 0.f;
    int uq = uid[bq];
    int uk = uid[bk];
    float v = (mq != 0.f && mk != 0.f && uq == uk) ? 1.f : 0.f;

    float qx = ref_pos[bq * 3 + 0], qy = ref_pos[bq * 3 + 1], qz = ref_pos[bq * 3 + 2];
    float kx = 0.f, ky = 0.f, kz = 0.f;
    if (inr) { kx = ref_pos[bk * 3 + 0]; ky = ref_pos[bk * 3 + 1]; kz = ref_pos[bk * 3 + 2]; }
    float dx = kx - qx, dy = ky - qy, dz = kz - qz;
    float dn = 1.f / (1.f + dx * dx + dy * dy + dz * dz);

    float p[16];
#pragma unroll
    for (int d = 0; d < 16; d++)
        p[d] = v * (dx * wpos[3 * d] + dy * wpos[3 * d + 1] + dz * wpos[3 * d + 2]
                    + dn * wdist[d] + wmk[d]);

    {   // cq (always)
        const float4* cq4 = (const float4*)(g_cq + (size_t)bq * 16);
#pragma unroll
        for (int i = 0; i < 4; i++) {
            float4 t = cq4[i];
            p[4 * i] += t.x; p[4 * i + 1] += t.y; p[4 * i + 2] += t.z; p[4 * i + 3] += t.w;
        }
    }
    if (inr) {  // z gather + ck (gated by key-in-range only)
        int tq = g_tok[bq], tk2 = g_tok[bk];
        const float4* zp4 = (const float4*)(g_z2p + (((size_t)(b * Tc + tq)) * Tc + tk2) * 16);
        const float4* ck4 = (const float4*)(g_ck + (size_t)bk * 16);
#pragma unroll
        for (int i = 0; i < 4; i++) {
            float4 t = zp4[i], u = ck4[i];
            p[4 * i]     += t.x + u.x;
            p[4 * i + 1] += t.y + u.y;
            p[4 * i + 2] += t.z + u.z;
            p[4 * i + 3] += t.w + u.w;
        }
    }

    // MLP: 3x (relu -> 16x16), packed f32x2 along j
    unsigned long long rp[8];
#pragma unroll
    for (int j = 0; j < 8; j++)
        rp[j] = pack2(fmaxf(p[2 * j], 0.f), fmaxf(p[2 * j + 1], 0.f));
    float m[16];
#pragma unroll
    for (int L = 0; L < 3; L++) {
        const unsigned long long* w2 = (const unsigned long long*)(wm + L * 256);
        float nm[16];
#pragma unroll
        for (int i = 0; i < 16; i++) {
            unsigned long long a = 0ull;
#pragma unroll
            for (int j = 0; j < 8; j++) fma2(a, rp[j], w2[i * 8 + j]);
            nm[i] = lo32(a) + hi32(a);
        }
        if (L < 2) {
#pragma unroll
            for (int j = 0; j < 8; j++)
                rp[j] = pack2(fmaxf(nm[2 * j], 0.f), fmaxf(nm[2 * j + 1], 0.f));
        } else {
#pragma unroll
            for (int i = 0; i < 16; i++) m[i] = nm[i];
        }
    }

    float4* o4 = (float4*)(out + (size_t)gidx * 16);
#pragma unroll
    for (int i = 0; i < 4; i++)
        o4[i] = make_float4(p[4 * i] + m[4 * i], p[4 * i + 1] + m[4 * i + 1],
                            p[4 * i + 2] + m[4 * i + 2], p[4 * i + 3] + m[4 * i + 3]);
}

// ---------------- launch ----------------
extern "C" void kernel_launch(void* const* d_in, const int* in_sizes, int n_in,
                              void* d_out, int out_size) {
    const float* ref_pos            = (const float*)d_in[0];
    const float* ref_charge         = (const float*)d_in[1];
    const float* atom_pad_mask      = (const float*)d_in[2];
    const float* ref_element        = (const float*)d_in[3];
    const float* ref_atom_name_chars= (const float*)d_in[4];
    const int*   ref_space_uid      = (const int*)  d_in[5];
    const float* atom_to_token      = (const float*)d_in[6];
    const float* s_trunk            = (const float*)d_in[7];
    const float* z                  = (const float*)d_in[8];
    const float* W_feat             = (const float*)d_in[9];
    const float* W_pos              = (const float*)d_in[10];
    const float* W_dist             = (const float*)d_in[11];
    const float* W_maskp            = (const float*)d_in[12];
    const float* ln_s_g             = (const float*)d_in[13];
    const float* ln_s_b             = (const float*)d_in[14];
    const float* W_s2c              = (const float*)d_in[15];
    const float* ln_z_g             = (const float*)d_in[16];
    const float* ln_z_b             = (const float*)d_in[17];
    const float* W_z2p              = (const float*)d_in[18];
    const float* W_cq               = (const float*)d_in[19];
    const float* W_ck               = (const float*)d_in[20];
    const float* W_m1               = (const float*)d_in[21];
    const float* W_m2               = (const float*)d_in[22];
    const float* W_m3               = (const float*)d_in[23];
    float* out = (float*)d_out;

    prep_kernel<<<64, 256>>>(W_feat, W_s2c, W_z2p, ln_z_g, ln_z_b);
    tok_kernel<<<(Bc * Nc * 32) / 256, 256>>>(atom_to_token);
    s2c_kernel<<<Bc * Tc, 128>>>(s_trunk, ln_s_g, ln_s_b);
    c_kernel<<<(Bc * Nc) / 16, 128>>>(ref_pos, ref_charge, atom_pad_mask,
                                      ref_element, ref_atom_name_chars, W_cq, W_ck);
    z2p_kernel<<<(Bc * Tc * Tc) / 64, 256>>>(z);
    main_kernel<<<(Bc * 128 * 32 * 128) / 256, 256>>>(ref_pos, atom_pad_mask, ref_space_uid,
                                                      W_pos, W_dist, W_maskp,
                                                      W_m1, W_m2, W_m3, out);
}

// round 4
// speedup vs baseline: 1.6962x; 1.6962x over previous
#include <cuda_runtime.h>
#include <cstdint>

#define Bc 2
#define Nc 4096
#define Tc 512
#define CAP 64

// ---------------- scratch (static device globals; no allocation) ----------------
__device__ float g_s2c[Bc * Tc * 128];                 // s_to_c
__device__ int   g_tok[Bc * Nc];                       // token index per atom
__device__ float g_cq[Bc * Nc * 16];                   // relu(c) @ W_cq.T
__device__ float g_ck[Bc * Nc * 16];                   // relu(c) @ W_ck.T
__device__ float g_z2pc[(size_t)Bc * Tc * CAP * 16];   // compact z2p window (4 MB)
__device__ int   g_lo[Bc * Tc];                        // key-token window start per (b,tq)
__device__ int   g_amin[Bc * Tc];
__device__ int   g_amax[Bc * Tc];
__device__ float g_WfeatT[392 * 128];                  // [fi][ch], rows 389..391 zero
__device__ float g_Ws2cT[384 * 128];
__device__ float g_gw[16 * 128];                       // W_z2p * ln_z_g (folded)
__device__ float g_gsum[16];
__device__ float g_bw[16];

// ---------------- f32x2 helpers ----------------
__device__ __forceinline__ unsigned long long pack2(float a, float b) {
    unsigned long long r;
    asm("mov.b64 %0, {%1,%2};" : "=l"(r) : "f"(a), "f"(b));
    return r;
}
__device__ __forceinline__ void fma2(unsigned long long& acc, unsigned long long a, unsigned long long b) {
    asm("fma.rn.f32x2 %0, %1, %2, %0;" : "+l"(acc) : "l"(a), "l"(b));
}
__device__ __forceinline__ float lo32(unsigned long long v) { return __uint_as_float((unsigned)(v & 0xffffffffu)); }
__device__ __forceinline__ float hi32(unsigned long long v) { return __uint_as_float((unsigned)(v >> 32)); }

// ---------------- prep: transposes + layernorm fold for z + range init ----------------
__global__ void prep_kernel(const float* __restrict__ W_feat, const float* __restrict__ W_s2c,
                            const float* __restrict__ W_z2p, const float* __restrict__ ln_z_g,
                            const float* __restrict__ ln_z_b) {
    int t = blockIdx.x * blockDim.x + threadIdx.x;
    int nt = gridDim.x * blockDim.x;
    for (int i = t; i < 392 * 128; i += nt) {
        int fi = i >> 7, ch = i & 127;
        g_WfeatT[i] = (fi < 389) ? W_feat[ch * 389 + fi] : 0.f;
    }
    for (int i = t; i < 384 * 128; i += nt) {
        int ch = i / 384, f = i % 384;
        g_Ws2cT[f * 128 + ch] = W_s2c[i];
    }
    for (int i = t; i < 16 * 128; i += nt) {
        g_gw[i] = W_z2p[i] * ln_z_g[i & 127];
    }
    for (int i = t; i < Bc * Tc; i += nt) { g_amin[i] = Nc; g_amax[i] = -1; }
    if (t < 16) {
        float gs = 0.f, bw = 0.f;
        for (int f = 0; f < 128; f++) {
            gs += W_z2p[t * 128 + f] * ln_z_g[f];
            bw += W_z2p[t * 128 + f] * ln_z_b[f];
        }
        g_gsum[t] = gs;
        g_bw[t] = bw;
    }
}

// ---------------- token index extraction (one-hot argmax), warp per atom ----------------
__global__ void tok_kernel(const float* __restrict__ a2t) {
    int warp = (blockIdx.x * blockDim.x + threadIdx.x) >> 5;
    int lane = threadIdx.x & 31;
    if (warp >= Bc * Nc) return;
    const float* row = a2t + (size_t)warp * Tc;
    int idx = 0;
    for (int i = lane; i < Tc; i += 32)
        if (row[i] > 0.5f) idx = i;
#pragma unroll
    for (int o = 16; o; o >>= 1) idx = max(idx, __shfl_xor_sync(0xffffffffu, idx, o));
    if (lane == 0) g_tok[warp] = idx;
}

// ---------------- per-(b,token) atom range via atomics ----------------
__global__ void minmax_kernel() {
    int idx = blockIdx.x * blockDim.x + threadIdx.x;
    if (idx >= Bc * Nc) return;
    int b = idx >> 12;
    int al = idx & (Nc - 1);
    int t = g_tok[idx];
    atomicMin(&g_amin[b * Tc + t], al);
    atomicMax(&g_amax[b * Tc + t], al);
}

// ---------------- key-token window start per (b,tq) ----------------
__global__ void lo_kernel() {
    int i = blockIdx.x * blockDim.x + threadIdx.x;
    if (i >= Bc * Tc) return;
    int b = i >> 9;
    int amx = g_amax[i];
    if (amx < 0) { g_lo[i] = 0; return; }
    int amn = g_amin[i];
    int kkmin = amn >> 5;
    int alo = 32 * kkmin - 48;
    if (alo < 0) alo = 0;
    g_lo[i] = g_tok[b * Nc + alo];
}

// ---------------- s_to_c: layernorm(s_trunk) @ W_s2c.T ----------------
__global__ void s2c_kernel(const float* __restrict__ s_trunk, const float* __restrict__ g,
                           const float* __restrict__ bta) {
    __shared__ __align__(16) float xs[384];
    __shared__ float red[8];
    int row = blockIdx.x;
    int tid = threadIdx.x;
    const float* x = s_trunk + (size_t)row * 384;
    float v0 = x[tid], v1 = x[tid + 128], v2 = x[tid + 256];
    float s = v0 + v1 + v2, s2 = v0 * v0 + v1 * v1 + v2 * v2;
#pragma unroll
    for (int o = 16; o; o >>= 1) {
        s += __shfl_xor_sync(0xffffffffu, s, o);
        s2 += __shfl_xor_sync(0xffffffffu, s2, o);
    }
    if ((tid & 31) == 0) { red[tid >> 5] = s; red[4 + (tid >> 5)] = s2; }
    __syncthreads();
    s = red[0] + red[1] + red[2] + red[3];
    s2 = red[4] + red[5] + red[6] + red[7];
    float mu = s * (1.f / 384.f);
    float var = s2 * (1.f / 384.f) - mu * mu;
    float rs = rsqrtf(var + 1e-5f);
    xs[tid]       = (v0 - mu) * rs * g[tid]       + bta[tid];
    xs[tid + 128] = (v1 - mu) * rs * g[tid + 128] + bta[tid + 128];
    xs[tid + 256] = (v2 - mu) * rs * g[tid + 256] + bta[tid + 256];
    __syncthreads();
    float acc = 0.f;
#pragma unroll 4
    for (int f = 0; f < 384; f++) acc += xs[f] * g_Ws2cT[f * 128 + tid];
    g_s2c[(size_t)row * 128 + tid] = acc;
}

// ---------------- c embedding + cq/ck heads (8 atoms per block, 256 threads, f32x2) ---
__global__ void __launch_bounds__(256) c_kernel(
        const float* __restrict__ ref_pos, const float* __restrict__ ref_charge,
        const float* __restrict__ amask, const float* __restrict__ elem,
        const float* __restrict__ chars,
        const float* __restrict__ W_cq, const float* __restrict__ W_ck) {
    // union: fsd[8][784] duplicated feats (25088B) / later cs[8][128] + wcs[2][16][130]
    __shared__ __align__(16) float sm[8 * 784];
    __shared__ int ts[8];
    int tid = threadIdx.x;
    int abase = blockIdx.x * 8;

#pragma unroll
    for (int pass = 0; pass < 2; pass++) {
        int fi = tid + pass * 256;
        if (fi < 392) {
#pragma unroll
            for (int a = 0; a < 8; a++) {
                int atom = abase + a;
                float v;
                if (fi < 3)        v = ref_pos[atom * 3 + fi];
                else if (fi == 3)  v = ref_charge[atom];
                else if (fi == 4)  v = amask[atom];
                else if (fi < 133) v = elem[(size_t)atom * 128 + (fi - 5)];
                else if (fi < 389) v = chars[(size_t)atom * 256 + (fi - 133)];
                else               v = 0.f;
                *(float2*)(sm + a * 784 + 2 * fi) = make_float2(v, v);
            }
        }
    }
    if (tid < 8) ts[tid] = g_tok[abase + tid];
    __syncthreads();

    int chp = tid & 63;       // channel pair, ch0 = 2*chp
    int ah  = tid >> 6;       // 0..3
    int a0 = ah, a1 = ah + 4;
    const ulonglong2* f0 = (const ulonglong2*)(sm + a0 * 784);
    const ulonglong2* f1 = (const ulonglong2*)(sm + a1 * 784);
    const float* wbase = g_WfeatT + 2 * chp;
    unsigned long long acc0 = 0, acc1 = 0;
#pragma unroll 4
    for (int f2 = 0; f2 < 196; f2++) {
        unsigned long long w0 = *(const unsigned long long*)(wbase + (2 * f2) * 128);
        unsigned long long w1 = *(const unsigned long long*)(wbase + (2 * f2 + 1) * 128);
        ulonglong2 pa = f0[f2];
        ulonglong2 pb = f1[f2];
        fma2(acc0, pa.x, w0);
        fma2(acc0, pa.y, w1);
        fma2(acc1, pb.x, w0);
        fma2(acc1, pb.y, w1);
    }

    int bb = abase >> 12;     // batch
    float2 sA = *(const float2*)(g_s2c + ((size_t)(bb * Tc + ts[a0])) * 128 + 2 * chp);
    float2 sB = *(const float2*)(g_s2c + ((size_t)(bb * Tc + ts[a1])) * 128 + 2 * chp);
    float c00 = fmaxf(lo32(acc0) + sA.x, 0.f);
    float c01 = fmaxf(hi32(acc0) + sA.y, 0.f);
    float c10 = fmaxf(lo32(acc1) + sB.x, 0.f);
    float c11 = fmaxf(hi32(acc1) + sB.y, 0.f);
    __syncthreads();

    float* cs  = sm;            // [8][128]
    float* wcs = sm + 1024;     // [2][16][130]
    *(float2*)(cs + a0 * 128 + 2 * chp) = make_float2(c00, c01);
    *(float2*)(cs + a1 * 128 + 2 * chp) = make_float2(c10, c11);
    for (int idx = tid; idx < 2 * 16 * 128; idx += 256) {
        int which = idx >> 11, i = (idx >> 7) & 15, ch = idx & 127;
        wcs[(which * 16 + i) * 130 + ch] = which ? W_ck[i * 128 + ch] : W_cq[i * 128 + ch];
    }
    __syncthreads();

    int i = tid & 15, which = (tid >> 4) & 1, a = tid >> 5;   // one output per thread
    const unsigned long long* wr = (const unsigned long long*)(wcs + (which * 16 + i) * 130);
    const unsigned long long* cr = (const unsigned long long*)(cs + a * 128);
    unsigned long long s = 0;
#pragma unroll 16
    for (int t2 = 0; t2 < 64; t2++) fma2(s, cr[t2], wr[t2]);
    float* dst = which ? g_ck : g_cq;
    dst[(size_t)(abase + a) * 16 + i] = lo32(s) + hi32(s);
}

// ---------------- compact z_to_p: one block per (b,tq), 64 key-token rows ----------------
__global__ void z2pc_kernel(const float* __restrict__ z) {
    __shared__ __align__(16) float xs[64 * 132];
    __shared__ __align__(16) float gws[16 * 130];
    __shared__ float mus[64], rss[64], gsum_s[16], bw_s[16];
    int tid = threadIdx.x;
    int bt = blockIdx.x;                 // b*Tc + tq
    int lo = g_lo[bt];

    for (int i = tid; i < 2048; i += 256)
        gws[(i >> 7) * 130 + (i & 127)] = g_gw[i];
    if (tid < 16) { gsum_s[tid] = g_gsum[tid]; bw_s[tid] = g_bw[tid]; }

    {
        int r = tid >> 2, j = tid & 3;
        int tk = lo + r;
        if (tk > Tc - 1) tk = Tc - 1;
        const float4* src = (const float4*)(z + ((size_t)bt * Tc + tk) * 128) + j * 8;
        float4* dst = (float4*)(xs + r * 132) + j * 8;
        float s = 0.f, s2 = 0.f;
#pragma unroll
        for (int q = 0; q < 8; q++) {
            float4 t = src[q];
            dst[q] = t;
            s += (t.x + t.y) + (t.z + t.w);
            s2 += t.x * t.x + t.y * t.y + t.z * t.z + t.w * t.w;
        }
        s  += __shfl_xor_sync(0xffffffffu, s, 1);
        s2 += __shfl_xor_sync(0xffffffffu, s2, 1);
        s  += __shfl_xor_sync(0xffffffffu, s, 2);
        s2 += __shfl_xor_sync(0xffffffffu, s2, 2);
        if (j == 0) {
            float mu = s * (1.f / 128.f);
            float var = s2 * (1.f / 128.f) - mu * mu;
            mus[r] = mu;
            rss[r] = rsqrtf(var + 1e-5f);
        }
    }
    __syncthreads();

    int ch = tid & 15, rb = tid >> 4;
    const unsigned long long* wp = (const unsigned long long*)(gws + ch * 130);
    const unsigned long long* x0 = (const unsigned long long*)(xs + (rb * 4 + 0) * 132);
    const unsigned long long* x1 = (const unsigned long long*)(xs + (rb * 4 + 1) * 132);
    const unsigned long long* x2 = (const unsigned long long*)(xs + (rb * 4 + 2) * 132);
    const unsigned long long* x3 = (const unsigned long long*)(xs + (rb * 4 + 3) * 132);
    unsigned long long a0 = 0, a1 = 0, a2 = 0, a3 = 0;
#pragma unroll 16
    for (int f2 = 0; f2 < 64; f2++) {
        unsigned long long w = wp[f2];
        fma2(a0, x0[f2], w);
        fma2(a1, x1[f2], w);
        fma2(a2, x2[f2], w);
        fma2(a3, x3[f2], w);
    }
    float gs = gsum_s[ch], bw = bw_s[ch];
    float dots[4] = { lo32(a0) + hi32(a0), lo32(a1) + hi32(a1),
                      lo32(a2) + hi32(a2), lo32(a3) + hi32(a3) };
#pragma unroll
    for (int i = 0; i < 4; i++) {
        int r = rb * 4 + i;
        g_z2pc[((size_t)bt * CAP + r) * 16 + ch] = rss[r] * (dots[i] - mus[r] * gs) + bw;
    }
}

// ---------------- rare-path exact z2p (window overflow fallback) ----------------
__device__ __noinline__ void z2p_direct(const float* __restrict__ z, int bt, int tk, float* zc) {
    const float* row = z + ((size_t)bt * Tc + tk) * 128;
    float s = 0.f, s2 = 0.f;
    for (int f = 0; f < 128; f++) { float x = row[f]; s += x; s2 += x * x; }
    float mu = s * (1.f / 128.f);
    float rs = rsqrtf(s2 * (1.f / 128.f) - mu * mu + 1e-5f);
    for (int d = 0; d < 16; d++) {
        float dot = 0.f;
        for (int f = 0; f < 128; f++) dot += row[f] * g_gw[d * 128 + f];
        zc[d] = rs * (dot - mu * g_gsum[d]) + g_bw[d];
    }
}

// ---------------- per-side p assembly ----------------
__device__ __forceinline__ void build_p(
        float* p, bool inr, int b, int bk, float mq, int uq,
        float qx, float qy, float qz, int tq, int lo,
        const float* __restrict__ amask, const int* __restrict__ uid,
        const float* __restrict__ ref_pos, const float* __restrict__ z,
        const float* wpos, const float* wdist, const float* wmk, const float4* cqv) {
    float mk = inr ? amask[bk] : 0.f;
    int uk = uid[bk];
    float v = (mq != 0.f && mk != 0.f && uq == uk) ? 1.f : 0.f;
    float kx = 0.f, ky = 0.f, kz = 0.f;
    if (inr) { kx = ref_pos[bk * 3]; ky = ref_pos[bk * 3 + 1]; kz = ref_pos[bk * 3 + 2]; }
    float dx = kx - qx, dy = ky - qy, dz = kz - qz;
    float dn = 1.f / (1.f + dx * dx + dy * dy + dz * dz);
#pragma unroll
    for (int d = 0; d < 16; d++)
        p[d] = v * (dx * wpos[3 * d] + dy * wpos[3 * d + 1] + dz * wpos[3 * d + 2]
                    + dn * wdist[d] + wmk[d]);
#pragma unroll
    for (int i = 0; i < 4; i++) {
        float4 t = cqv[i];
        p[4 * i] += t.x; p[4 * i + 1] += t.y; p[4 * i + 2] += t.z; p[4 * i + 3] += t.w;
    }
    if (inr) {
        int tk2 = g_tok[bk];
        int j = tk2 - lo;
        const float4* ck4 = (const float4*)(g_ck + (size_t)bk * 16);
        if (j < CAP) {
            const float4* zp4 = (const float4*)(g_z2pc + (((size_t)(b * Tc + tq)) * CAP + j) * 16);
#pragma unroll
            for (int i = 0; i < 4; i++) {
                float4 t = zp4[i], u = ck4[i];
                p[4 * i]     += t.x + u.x;
                p[4 * i + 1] += t.y + u.y;
                p[4 * i + 2] += t.z + u.z;
                p[4 * i + 3] += t.w + u.w;
            }
        } else {
            float zc[16];
            z2p_direct(z, b * Tc + tq, tk2, zc);
#pragma unroll
            for (int i = 0; i < 4; i++) {
                float4 u = ck4[i];
                p[4 * i]     += zc[4 * i]     + u.x;
                p[4 * i + 1] += zc[4 * i + 1] + u.y;
                p[4 * i + 2] += zc[4 * i + 2] + u.z;
                p[4 * i + 3] += zc[4 * i + 3] + u.w;
            }
        }
    }
}

// ---------------- main: 2 positions per thread (same query), i-outer MLP ----------------
__global__ void __launch_bounds__(256) main_kernel(
        const float* __restrict__ ref_pos, const float* __restrict__ amask,
        const int* __restrict__ uid, const float* __restrict__ z,
        const float* __restrict__ W_pos, const float* __restrict__ W_dist,
        const float* __restrict__ W_maskp,
        const float* __restrict__ W_m1, const float* __restrict__ W_m2,
        const float* __restrict__ W_m3,
        float* __restrict__ out) {
    __shared__ __align__(16) float wm[3 * 256];
    __shared__ float wpos[48], wdist[16], wmk[16];
    int tid = threadIdx.x;
    wm[tid] = W_m1[tid];
    wm[256 + tid] = W_m2[tid];
    wm[512 + tid] = W_m3[tid];
    if (tid < 48) wpos[tid] = W_pos[tid];
    if (tid < 16) { wdist[tid] = W_dist[tid]; wmk[tid] = W_maskp[tid]; }
    __syncthreads();

    int qloc = tid >> 6, h0 = tid & 63;
    int g0 = blockIdx.x * 512 + qloc * 128 + h0;        // position A; B = g0 + 64
    int ww = (g0 >> 7) & 31;
    int kk = (g0 >> 12) & 127;
    int b  = g0 >> 19;
    int q = kk * 32 + ww;
    int bq = b * Nc + q;
    int keyA = kk * 32 + h0 - 48;
    int keyB = keyA + 64;
    bool inrA = keyA >= 0;                              // keyA <= 4079 < Nc always
    bool inrB = keyB < Nc;                              // keyB >= 16 always
    int bkA = b * Nc + (inrA ? keyA : 0);
    int bkB = b * Nc + (inrB ? keyB : 0);

    float mq = amask[bq];
    int uq = uid[bq];
    float qx = ref_pos[bq * 3], qy = ref_pos[bq * 3 + 1], qz = ref_pos[bq * 3 + 2];
    int tq = g_tok[bq];
    int lo = g_lo[b * Tc + tq];
    const float4* cq4 = (const float4*)(g_cq + (size_t)bq * 16);
    float4 cqv[4] = { cq4[0], cq4[1], cq4[2], cq4[3] };

    float pA[16], pB[16];
    build_p(pA, inrA, b, bkA, mq, uq, qx, qy, qz, tq, lo, amask, uid, ref_pos, z,
            wpos, wdist, wmk, cqv);
    build_p(pB, inrB, b, bkB, mq, uq, qx, qy, qz, tq, lo, amask, uid, ref_pos, z,
            wpos, wdist, wmk, cqv);

    unsigned long long rpA[8], rpB[8];
#pragma unroll
    for (int j = 0; j < 8; j++) {
        rpA[j] = pack2(fmaxf(pA[2 * j], 0.f), fmaxf(pA[2 * j + 1], 0.f));
        rpB[j] = pack2(fmaxf(pB[2 * j], 0.f), fmaxf(pB[2 * j + 1], 0.f));
    }
    float mA[16], mB[16];
#pragma unroll
    for (int L = 0; L < 3; L++) {
        const unsigned long long* w2 = (const unsigned long long*)(wm + L * 256);
        float nmA[16], nmB[16];
#pragma unroll
        for (int i = 0; i < 16; i++) {
            unsigned long long aA = 0ull, aB = 0ull;
#pragma unroll
            for (int j = 0; j < 8; j++) {
                unsigned long long wv = w2[i * 8 + j];
                fma2(aA, rpA[j], wv);
                fma2(aB, rpB[j], wv);
            }
            nmA[i] = lo32(aA) + hi32(aA);
            nmB[i] = lo32(aB) + hi32(aB);
        }
        if (L < 2) {
#pragma unroll
            for (int j = 0; j < 8; j++) {
                rpA[j] = pack2(fmaxf(nmA[2 * j], 0.f), fmaxf(nmA[2 * j + 1], 0.f));
                rpB[j] = pack2(fmaxf(nmB[2 * j], 0.f), fmaxf(nmB[2 * j + 1], 0.f));
            }
        } else {
#pragma unroll
            for (int i = 0; i < 16; i++) { mA[i] = nmA[i]; mB[i] = nmB[i]; }
        }
    }

    float4* oA = (float4*)(out + (size_t)g0 * 16);
    float4* oB = (float4*)(out + (size_t)(g0 + 64) * 16);
#pragma unroll
    for (int i = 0; i < 4; i++) {
        oA[i] = make_float4(pA[4 * i] + mA[4 * i], pA[4 * i + 1] + mA[4 * i + 1],
                            pA[4 * i + 2] + mA[4 * i + 2], pA[4 * i + 3] + mA[4 * i + 3]);
        oB[i] = make_float4(pB[4 * i] + mB[4 * i], pB[4 * i + 1] + mB[4 * i + 1],
                            pB[4 * i + 2] + mB[4 * i + 2], pB[4 * i + 3] + mB[4 * i + 3]);
    }
}

// ---------------- launch ----------------
extern "C" void kernel_launch(void* const* d_in, const int* in_sizes, int n_in,
                              void* d_out, int out_size) {
    const float* ref_pos             = (const float*)d_in[0];
    const float* ref_charge          = (const float*)d_in[1];
    const float* atom_pad_mask       = (const float*)d_in[2];
    const float* ref_element         = (const float*)d_in[3];
    const float* ref_atom_name_chars = (const float*)d_in[4];
    const int*   ref_space_uid       = (const int*)  d_in[5];
    const float* atom_to_token       = (const float*)d_in[6];
    const float* s_trunk             = (const float*)d_in[7];
    const float* z                   = (const float*)d_in[8];
    const float* W_feat              = (const float*)d_in[9];
    const float* W_pos               = (const float*)d_in[10];
    const float* W_dist              = (const float*)d_in[11];
    const float* W_maskp             = (const float*)d_in[12];
    const float* ln_s_g              = (const float*)d_in[13];
    const float* ln_s_b              = (const float*)d_in[14];
    const float* W_s2c               = (const float*)d_in[15];
    const float* ln_z_g              = (const float*)d_in[16];
    const float* ln_z_b              = (const float*)d_in[17];
    const float* W_z2p               = (const float*)d_in[18];
    const float* W_cq                = (const float*)d_in[19];
    const float* W_ck                = (const float*)d_in[20];
    const float* W_m1                = (const float*)d_in[21];
    const float* W_m2                = (const float*)d_in[22];
    const float* W_m3                = (const float*)d_in[23];
    float* out = (float*)d_out;

    prep_kernel<<<64, 256>>>(W_feat, W_s2c, W_z2p, ln_z_g, ln_z_b);
    tok_kernel<<<(Bc * Nc * 32) / 256, 256>>>(atom_to_token);
    minmax_kernel<<<(Bc * Nc) / 256, 256>>>();
    lo_kernel<<<4, 256>>>();
    s2c_kernel<<<Bc * Tc, 128>>>(s_trunk, ln_s_g, ln_s_b);
    c_kernel<<<(Bc * Nc) / 8, 256>>>(ref_pos, ref_charge, atom_pad_mask,
                                     ref_element, ref_atom_name_chars, W_cq, W_ck);
    z2pc_kernel<<<Bc * Tc, 256>>>(z);
    main_kernel<<<(Bc * 128 * 32 * 128) / 512, 256>>>(ref_pos, atom_pad_mask, ref_space_uid, z,
                                                      W_pos, W_dist, W_maskp,
                                                      W_m1, W_m2, W_m3, out);
}

// round 5
// speedup vs baseline: 1.8444x; 1.0874x over previous
#include <cuda_runtime.h>
#include <cstdint>

#define Bc 2
#define Nc 4096
#define Tc 512
#define CAP 64

// ---------------- scratch (static device globals; no allocation) ----------------
__device__ float g_s2c[Bc * Tc * 128];                 // s_to_c
__device__ int   g_tok[Bc * Nc];                       // token index per atom
__device__ float g_cq[Bc * Nc * 16];                   // relu(c) @ W_cq.T
__device__ float g_ck[Bc * Nc * 16];                   // relu(c) @ W_ck.T
__device__ float g_z2pc[(size_t)Bc * Tc * CAP * 16];   // compact z2p window (4 MB)
__device__ int   g_lo[Bc * Tc];                        // key-token window start per (b,tq)
__device__ int   g_amin[Bc * Tc];
__device__ int   g_amax[Bc * Tc];
__device__ float g_WfeatT[392 * 128];                  // [fi][ch], rows 389..391 zero
__device__ float g_Ws2cT[384 * 128];
__device__ float g_gw[16 * 128];                       // W_z2p * ln_z_g (folded)
__device__ float g_gsum[16];
__device__ float g_bw[16];

// ---------------- f32x2 / bf16 helpers ----------------
__device__ __forceinline__ unsigned long long pack2(float a, float b) {
    unsigned long long r;
    asm("mov.b64 %0, {%1,%2};" : "=l"(r) : "f"(a), "f"(b));
    return r;
}
__device__ __forceinline__ void fma2(unsigned long long& acc, unsigned long long a, unsigned long long b) {
    asm("fma.rn.f32x2 %0, %1, %2, %0;" : "+l"(acc) : "l"(a), "l"(b));
}
__device__ __forceinline__ float lo32(unsigned long long v) { return __uint_as_float((unsigned)(v & 0xffffffffu)); }
__device__ __forceinline__ float hi32(unsigned long long v) { return __uint_as_float((unsigned)(v >> 32)); }
// pack two floats into bf16x2 (lo in lower half)
__device__ __forceinline__ unsigned pkbf(float lo, float hi) {
    unsigned r;
    asm("cvt.rn.bf16x2.f32 %0, %1, %2;" : "=r"(r) : "f"(hi), "f"(lo));
    return r;
}
// D(16x8,f32) = A(16x16,bf16 row) * B(16x8,bf16 col) + 0
__device__ __forceinline__ void mma16816(float* d, unsigned a0, unsigned a1, unsigned a2, unsigned a3,
                                         unsigned b0, unsigned b1) {
    asm("mma.sync.aligned.m16n8k16.row.col.f32.bf16.bf16.f32 "
        "{%0,%1,%2,%3}, {%4,%5,%6,%7}, {%8,%9}, {%10,%11,%12,%13};"
        : "=f"(d[0]), "=f"(d[1]), "=f"(d[2]), "=f"(d[3])
        : "r"(a0), "r"(a1), "r"(a2), "r"(a3), "r"(b0), "r"(b1),
          "f"(0.f), "f"(0.f), "f"(0.f), "f"(0.f));
}

// ---------------- prep: transposes + layernorm fold for z + range init ----------------
__global__ void prep_kernel(const float* __restrict__ W_feat, const float* __restrict__ W_s2c,
                            const float* __restrict__ W_z2p, const float* __restrict__ ln_z_g,
                            const float* __restrict__ ln_z_b) {
    int t = blockIdx.x * blockDim.x + threadIdx.x;
    int nt = gridDim.x * blockDim.x;
    for (int i = t; i < 392 * 128; i += nt) {
        int fi = i >> 7, ch = i & 127;
        g_WfeatT[i] = (fi < 389) ? W_feat[ch * 389 + fi] : 0.f;
    }
    for (int i = t; i < 384 * 128; i += nt) {
        int ch = i / 384, f = i % 384;
        g_Ws2cT[f * 128 + ch] = W_s2c[i];
    }
    for (int i = t; i < 16 * 128; i += nt) {
        g_gw[i] = W_z2p[i] * ln_z_g[i & 127];
    }
    for (int i = t; i < Bc * Tc; i += nt) { g_amin[i] = Nc; g_amax[i] = -1; }
    if (t < 16) {
        float gs = 0.f, bw = 0.f;
        for (int f = 0; f < 128; f++) {
            gs += W_z2p[t * 128 + f] * ln_z_g[f];
            bw += W_z2p[t * 128 + f] * ln_z_b[f];
        }
        g_gsum[t] = gs;
        g_bw[t] = bw;
    }
}

// ---------------- token index (one-hot argmax) + per-token atom range, warp per atom ----
__global__ void tok_kernel(const float* __restrict__ a2t) {
    int warp = (blockIdx.x * blockDim.x + threadIdx.x) >> 5;
    int lane = threadIdx.x & 31;
    if (warp >= Bc * Nc) return;
    const float4* row = (const float4*)(a2t + (size_t)warp * Tc);
    int idx = 0;
#pragma unroll
    for (int i = 0; i < 4; i++) {
        float4 v = row[lane + 32 * i];
        int base = 4 * (lane + 32 * i);
        if (v.x > 0.5f) idx = base;
        if (v.y > 0.5f) idx = base + 1;
        if (v.z > 0.5f) idx = base + 2;
        if (v.w > 0.5f) idx = base + 3;
    }
#pragma unroll
    for (int o = 16; o; o >>= 1) idx = max(idx, __shfl_xor_sync(0xffffffffu, idx, o));
    if (lane == 0) {
        g_tok[warp] = idx;
        int b = warp >> 12;
        int al = warp & (Nc - 1);
        atomicMin(&g_amin[b * Tc + idx], al);
        atomicMax(&g_amax[b * Tc + idx], al);
    }
}

// ---------------- s_to_c: layernorm(s_trunk) @ W_s2c.T ----------------
__global__ void s2c_kernel(const float* __restrict__ s_trunk, const float* __restrict__ g,
                           const float* __restrict__ bta) {
    __shared__ __align__(16) float xs[384];
    __shared__ float red[8];
    int row = blockIdx.x;
    int tid = threadIdx.x;
    const float* x = s_trunk + (size_t)row * 384;
    float v0 = x[tid], v1 = x[tid + 128], v2 = x[tid + 256];
    float s = v0 + v1 + v2, s2 = v0 * v0 + v1 * v1 + v2 * v2;
#pragma unroll
    for (int o = 16; o; o >>= 1) {
        s += __shfl_xor_sync(0xffffffffu, s, o);
        s2 += __shfl_xor_sync(0xffffffffu, s2, o);
    }
    if ((tid & 31) == 0) { red[tid >> 5] = s; red[4 + (tid >> 5)] = s2; }
    __syncthreads();
    s = red[0] + red[1] + red[2] + red[3];
    s2 = red[4] + red[5] + red[6] + red[7];
    float mu = s * (1.f / 384.f);
    float var = s2 * (1.f / 384.f) - mu * mu;
    float rs = rsqrtf(var + 1e-5f);
    xs[tid]       = (v0 - mu) * rs * g[tid]       + bta[tid];
    xs[tid + 128] = (v1 - mu) * rs * g[tid + 128] + bta[tid + 128];
    xs[tid + 256] = (v2 - mu) * rs * g[tid + 256] + bta[tid + 256];
    __syncthreads();
    float acc = 0.f;
#pragma unroll 4
    for (int f = 0; f < 384; f++) acc += xs[f] * g_Ws2cT[f * 128 + tid];
    g_s2c[(size_t)row * 128 + tid] = acc;
}

// ---------------- c embedding + cq/ck heads (8 atoms per block, 256 threads, f32x2) ---
__global__ void __launch_bounds__(256) c_kernel(
        const float* __restrict__ ref_pos, const float* __restrict__ ref_charge,
        const float* __restrict__ amask, const float* __restrict__ elem,
        const float* __restrict__ chars,
        const float* __restrict__ W_cq, const float* __restrict__ W_ck) {
    __shared__ __align__(16) float sm[8 * 784];
    __shared__ int ts[8];
    int tid = threadIdx.x;
    int abase = blockIdx.x * 8;

#pragma unroll
    for (int pass = 0; pass < 2; pass++) {
        int fi = tid + pass * 256;
        if (fi < 392) {
#pragma unroll
            for (int a = 0; a < 8; a++) {
                int atom = abase + a;
                float v;
                if (fi < 3)        v = ref_pos[atom * 3 + fi];
                else if (fi == 3)  v = ref_charge[atom];
                else if (fi == 4)  v = amask[atom];
                else if (fi < 133) v = elem[(size_t)atom * 128 + (fi - 5)];
                else if (fi < 389) v = chars[(size_t)atom * 256 + (fi - 133)];
                else               v = 0.f;
                *(float2*)(sm + a * 784 + 2 * fi) = make_float2(v, v);
            }
        }
    }
    if (tid < 8) ts[tid] = g_tok[abase + tid];
    __syncthreads();

    int chp = tid & 63;
    int ah  = tid >> 6;
    int a0 = ah, a1 = ah + 4;
    const ulonglong2* f0 = (const ulonglong2*)(sm + a0 * 784);
    const ulonglong2* f1 = (const ulonglong2*)(sm + a1 * 784);
    const float* wbase = g_WfeatT + 2 * chp;
    unsigned long long acc0 = 0, acc1 = 0;
#pragma unroll 4
    for (int f2 = 0; f2 < 196; f2++) {
        unsigned long long w0 = *(const unsigned long long*)(wbase + (2 * f2) * 128);
        unsigned long long w1 = *(const unsigned long long*)(wbase + (2 * f2 + 1) * 128);
        ulonglong2 pa = f0[f2];
        ulonglong2 pb = f1[f2];
        fma2(acc0, pa.x, w0);
        fma2(acc0, pa.y, w1);
        fma2(acc1, pb.x, w0);
        fma2(acc1, pb.y, w1);
    }

    int bb = abase >> 12;
    float2 sA = *(const float2*)(g_s2c + ((size_t)(bb * Tc + ts[a0])) * 128 + 2 * chp);
    float2 sB = *(const float2*)(g_s2c + ((size_t)(bb * Tc + ts[a1])) * 128 + 2 * chp);
    float c00 = fmaxf(lo32(acc0) + sA.x, 0.f);
    float c01 = fmaxf(hi32(acc0) + sA.y, 0.f);
    float c10 = fmaxf(lo32(acc1) + sB.x, 0.f);
    float c11 = fmaxf(hi32(acc1) + sB.y, 0.f);
    __syncthreads();

    float* cs  = sm;            // [8][128]
    float* wcs = sm + 1024;     // [2][16][130]
    *(float2*)(cs + a0 * 128 + 2 * chp) = make_float2(c00, c01);
    *(float2*)(cs + a1 * 128 + 2 * chp) = make_float2(c10, c11);
    for (int idx = tid; idx < 2 * 16 * 128; idx += 256) {
        int which = idx >> 11, i = (idx >> 7) & 15, ch = idx & 127;
        wcs[(which * 16 + i) * 130 + ch] = which ? W_ck[i * 128 + ch] : W_cq[i * 128 + ch];
    }
    __syncthreads();

    int i = tid & 15, which = (tid >> 4) & 1, a = tid >> 5;
    const unsigned long long* wr = (const unsigned long long*)(wcs + (which * 16 + i) * 130);
    const unsigned long long* cr = (const unsigned long long*)(cs + a * 128);
    unsigned long long s = 0;
#pragma unroll 16
    for (int t2 = 0; t2 < 64; t2++) fma2(s, cr[t2], wr[t2]);
    float* dst = which ? g_ck : g_cq;
    dst[(size_t)(abase + a) * 16 + i] = lo32(s) + hi32(s);
}

// ---------------- compact z_to_p: one block per (b,tq); computes its own lo ----------------
__global__ void z2pc_kernel(const float* __restrict__ z) {
    __shared__ __align__(16) float xs[64 * 132];
    __shared__ __align__(16) float gws[16 * 130];
    __shared__ float mus[64], rss[64], gsum_s[16], bw_s[16];
    __shared__ int lo_s;
    int tid = threadIdx.x;
    int bt = blockIdx.x;                 // b*Tc + tq

    if (tid == 0) {
        int lo = 0;
        int amx = g_amax[bt];
        if (amx >= 0) {
            int kkmin = g_amin[bt] >> 5;
            int alo = 32 * kkmin - 48;
            if (alo < 0) alo = 0;
            lo = g_tok[(bt >> 9) * Nc + alo];
        }
        g_lo[bt] = lo;
        lo_s = lo;
    }
    for (int i = tid; i < 2048; i += 256)
        gws[(i >> 7) * 130 + (i & 127)] = g_gw[i];
    if (tid < 16) { gsum_s[tid] = g_gsum[tid]; bw_s[tid] = g_bw[tid]; }
    __syncthreads();
    int lo = lo_s;

    {
        int r = tid >> 2, j = tid & 3;
        int tk = lo + r;
        if (tk > Tc - 1) tk = Tc - 1;
        const float4* src = (const float4*)(z + ((size_t)bt * Tc + tk) * 128) + j * 8;
        float4* dst = (float4*)(xs + r * 132) + j * 8;
        float s = 0.f, s2 = 0.f;
#pragma unroll
        for (int q = 0; q < 8; q++) {
            float4 t = src[q];
            dst[q] = t;
            s += (t.x + t.y) + (t.z + t.w);
            s2 += t.x * t.x + t.y * t.y + t.z * t.z + t.w * t.w;
        }
        s  += __shfl_xor_sync(0xffffffffu, s, 1);
        s2 += __shfl_xor_sync(0xffffffffu, s2, 1);
        s  += __shfl_xor_sync(0xffffffffu, s, 2);
        s2 += __shfl_xor_sync(0xffffffffu, s2, 2);
        if (j == 0) {
            float mu = s * (1.f / 128.f);
            float var = s2 * (1.f / 128.f) - mu * mu;
            mus[r] = mu;
            rss[r] = rsqrtf(var + 1e-5f);
        }
    }
    __syncthreads();

    int ch = tid & 15, rb = tid >> 4;
    const unsigned long long* wp = (const unsigned long long*)(gws + ch * 130);
    const unsigned long long* x0 = (const unsigned long long*)(xs + (rb * 4 + 0) * 132);
    const unsigned long long* x1 = (const unsigned long long*)(xs + (rb * 4 + 1) * 132);
    const unsigned long long* x2 = (const unsigned long long*)(xs + (rb * 4 + 2) * 132);
    const unsigned long long* x3 = (const unsigned long long*)(xs + (rb * 4 + 3) * 132);
    unsigned long long a0 = 0, a1 = 0, a2 = 0, a3 = 0;
#pragma unroll 16
    for (int f2 = 0; f2 < 64; f2++) {
        unsigned long long w = wp[f2];
        fma2(a0, x0[f2], w);
        fma2(a1, x1[f2], w);
        fma2(a2, x2[f2], w);
        fma2(a3, x3[f2], w);
    }
    float gs = gsum_s[ch], bw = bw_s[ch];
    float dots[4] = { lo32(a0) + hi32(a0), lo32(a1) + hi32(a1),
                      lo32(a2) + hi32(a2), lo32(a3) + hi32(a3) };
#pragma unroll
    for (int i = 0; i < 4; i++) {
        int r = rb * 4 + i;
        g_z2pc[((size_t)bt * CAP + r) * 16 + ch] = rss[r] * (dots[i] - mus[r] * gs) + bw;
    }
}

// ---------------- rare-path exact z2p (window overflow fallback) ----------------
__device__ __noinline__ void z2p_direct(const float* __restrict__ z, int bt, int tk, float* zc) {
    const float* row = z + ((size_t)bt * Tc + tk) * 128;
    float s = 0.f, s2 = 0.f;
    for (int f = 0; f < 128; f++) { float x = row[f]; s += x; s2 += x * x; }
    float mu = s * (1.f / 128.f);
    float rs = rsqrtf(s2 * (1.f / 128.f) - mu * mu + 1e-5f);
    for (int d = 0; d < 16; d++) {
        float dot = 0.f;
        for (int f = 0; f < 128; f++) dot += row[f] * g_gw[d * 128 + f];
        zc[d] = rs * (dot - mu * g_gsum[d]) + g_bw[d];
    }
}

// ---------------- main: 1 position per thread; MLP via warp mma (bf16, f32 accum) ----
__global__ void __launch_bounds__(256) main_kernel(
        const float* __restrict__ ref_pos, const float* __restrict__ amask,
        const int* __restrict__ uid, const float* __restrict__ z,
        const float* __restrict__ W_pos, const float* __restrict__ W_dist,
        const float* __restrict__ W_maskp,
        const float* __restrict__ W_m1, const float* __restrict__ W_m2,
        const float* __restrict__ W_m3,
        float* __restrict__ out) {
    __shared__ float wpos[48], wdist[16], wmk[16];
    __shared__ __align__(16) float msm[8 * 640];   // per warp: 32 rows x 20 floats
    int tid = threadIdx.x;
    int lane = tid & 31, wid = tid >> 5;
    int g = lane >> 2, t = lane & 3;
    if (tid < 48) wpos[tid] = W_pos[tid];
    if (tid < 16) { wdist[tid] = W_dist[tid]; wmk[tid] = W_maskp[tid]; }

    // weight fragments: B col-major k16xn8; B[k][n] = W[n][k]
    unsigned bf[3][4];
#pragma unroll
    for (int L = 0; L < 3; L++) {
        const float* W = (L == 0) ? W_m1 : (L == 1) ? W_m2 : W_m3;
        float2 w00 = *(const float2*)(W + g * 16 + 2 * t);
        float2 w01 = *(const float2*)(W + g * 16 + 2 * t + 8);
        float2 w10 = *(const float2*)(W + (g + 8) * 16 + 2 * t);
        float2 w11 = *(const float2*)(W + (g + 8) * 16 + 2 * t + 8);
        bf[L][0] = pkbf(w00.x, w00.y);   // n-lo, k 2t..2t+1
        bf[L][1] = pkbf(w01.x, w01.y);   // n-lo, k 2t+8..2t+9
        bf[L][2] = pkbf(w10.x, w10.y);   // n-hi, k 2t..2t+1
        bf[L][3] = pkbf(w11.x, w11.y);   // n-hi, k 2t+8..2t+9
    }
    __syncthreads();

    // ---- build p[16] for this position ----
    int gidx = blockIdx.x * 256 + tid;
    int hh = gidx & 127;
    int ww = (gidx >> 7) & 31;
    int kk = (gidx >> 12) & 127;
    int b  = gidx >> 19;
    int q = kk * 32 + ww;
    int bq = b * Nc + q;
    int key = kk * 32 + hh - 48;
    bool inr = (unsigned)key < (unsigned)Nc;
    int bk = b * Nc + (inr ? key : 0);

    float mq = amask[bq];
    float mk = inr ? amask[bk] : 0.f;
    int uq = uid[bq];
    int uk = uid[bk];
    float v = (mq != 0.f && mk != 0.f && uq == uk) ? 1.f : 0.f;

    float qx = ref_pos[bq * 3], qy = ref_pos[bq * 3 + 1], qz = ref_pos[bq * 3 + 2];
    float kx = 0.f, ky = 0.f, kz = 0.f;
    if (inr) { kx = ref_pos[bk * 3]; ky = ref_pos[bk * 3 + 1]; kz = ref_pos[bk * 3 + 2]; }
    float dx = kx - qx, dy = ky - qy, dz = kz - qz;
    float dn = 1.f / (1.f + dx * dx + dy * dy + dz * dz);

    float p[16];
#pragma unroll
    for (int d = 0; d < 16; d++)
        p[d] = v * (dx * wpos[3 * d] + dy * wpos[3 * d + 1] + dz * wpos[3 * d + 2]
                    + dn * wdist[d] + wmk[d]);
    {
        const float4* cq4 = (const float4*)(g_cq + (size_t)bq * 16);
#pragma unroll
        for (int i = 0; i < 4; i++) {
            float4 tt = cq4[i];
            p[4 * i] += tt.x; p[4 * i + 1] += tt.y; p[4 * i + 2] += tt.z; p[4 * i + 3] += tt.w;
        }
    }
    if (inr) {
        int tq = g_tok[bq];
        int lo = g_lo[b * Tc + tq];
        int tk2 = g_tok[bk];
        int j = tk2 - lo;
        const float4* ck4 = (const float4*)(g_ck + (size_t)bk * 16);
        if (j < CAP) {
            const float4* zp4 = (const float4*)(g_z2pc + (((size_t)(b * Tc + tq)) * CAP + j) * 16);
#pragma unroll
            for (int i = 0; i < 4; i++) {
                float4 tt = zp4[i], u = ck4[i];
                p[4 * i]     += tt.x + u.x;
                p[4 * i + 1] += tt.y + u.y;
                p[4 * i + 2] += tt.z + u.z;
                p[4 * i + 3] += tt.w + u.w;
            }
        } else {
            float zc[16];
            z2p_direct(z, b * Tc + tq, tk2, zc);
#pragma unroll
            for (int i = 0; i < 4; i++) {
                float4 u = ck4[i];
                p[4 * i]     += zc[4 * i]     + u.x;
                p[4 * i + 1] += zc[4 * i + 1] + u.y;
                p[4 * i + 2] += zc[4 * i + 2] + u.z;
                p[4 * i + 3] += zc[4 * i + 3] + u.w;
            }
        }
    }

    // ---- stage relu(p) as bf16 rows: warp-local [32 rows x 10 b32 units] ----
    float* wsm = msm + wid * 640;
    unsigned* h2 = (unsigned*)wsm;
#pragma unroll
    for (int j2 = 0; j2 < 8; j2++)
        h2[lane * 10 + j2] = pkbf(fmaxf(p[2 * j2], 0.f), fmaxf(p[2 * j2 + 1], 0.f));
    __syncwarp();

    // load A fragments for both 16-row tiles before any overwrite
    unsigned a0[2], a1[2], a2[2], a3[2];
#pragma unroll
    for (int tt = 0; tt < 2; tt++) {
        int rt = tt * 16;
        a0[tt] = h2[(rt + g) * 10 + t];
        a1[tt] = h2[(rt + g + 8) * 10 + t];
        a2[tt] = h2[(rt + g) * 10 + t + 4];
        a3[tt] = h2[(rt + g + 8) * 10 + t + 4];
    }
    __syncwarp();

    // ---- 3-layer MLP per tile via mma; epilogue stores f32 into same smem ----
#pragma unroll
    for (int tt = 0; tt < 2; tt++) {
        unsigned u0 = a0[tt], u1 = a1[tt], u2 = a2[tt], u3 = a3[tt];
        float dlo[4], dhi[4];
#pragma unroll
        for (int L = 0; L < 3; L++) {
            mma16816(dlo, u0, u1, u2, u3, bf[L][0], bf[L][1]);
            mma16816(dhi, u0, u1, u2, u3, bf[L][2], bf[L][3]);
            if (L < 2) {
                u0 = pkbf(fmaxf(dlo[0], 0.f), fmaxf(dlo[1], 0.f));
                u1 = pkbf(fmaxf(dlo[2], 0.f), fmaxf(dlo[3], 0.f));
                u2 = pkbf(fmaxf(dhi[0], 0.f), fmaxf(dhi[1], 0.f));
                u3 = pkbf(fmaxf(dhi[2], 0.f), fmaxf(dhi[3], 0.f));
            }
        }
        int r0 = tt * 16 + g, r1 = r0 + 8;
        *(float2*)(wsm + r0 * 20 + 2 * t)     = make_float2(dlo[0], dlo[1]);
        *(float2*)(wsm + r1 * 20 + 2 * t)     = make_float2(dlo[2], dlo[3]);
        *(float2*)(wsm + r0 * 20 + 8 + 2 * t) = make_float2(dhi[0], dhi[1]);
        *(float2*)(wsm + r1 * 20 + 8 + 2 * t) = make_float2(dhi[2], dhi[3]);
    }
    __syncwarp();

    // ---- out = p + m ----
    float4* o4 = (float4*)(out + (size_t)gidx * 16);
    const float4* mrow = (const float4*)(wsm + lane * 20);
#pragma unroll
    for (int i = 0; i < 4; i++) {
        float4 mi = mrow[i];
        o4[i] = make_float4(p[4 * i] + mi.x, p[4 * i + 1] + mi.y,
                            p[4 * i + 2] + mi.z, p[4 * i + 3] + mi.w);
    }
}

// ---------------- launch ----------------
extern "C" void kernel_launch(void* const* d_in, const int* in_sizes, int n_in,
                              void* d_out, int out_size) {
    const float* ref_pos             = (const float*)d_in[0];
    const float* ref_charge          = (const float*)d_in[1];
    const float* atom_pad_mask       = (const float*)d_in[2];
    const float* ref_element         = (const float*)d_in[3];
    const float* ref_atom_name_chars = (const float*)d_in[4];
    const int*   ref_space_uid       = (const int*)  d_in[5];
    const float* atom_to_token       = (const float*)d_in[6];
    const float* s_trunk             = (const float*)d_in[7];
    const float* z                   = (const float*)d_in[8];
    const float* W_feat              = (const float*)d_in[9];
    const float* W_pos               = (const float*)d_in[10];
    const float* W_dist              = (const float*)d_in[11];
    const float* W_maskp             = (const float*)d_in[12];
    const float* ln_s_g              = (const float*)d_in[13];
    const float* ln_s_b              = (const float*)d_in[14];
    const float* W_s2c               = (const float*)d_in[15];
    const float* ln_z_g              = (const float*)d_in[16];
    const float* ln_z_b              = (const float*)d_in[17];
    const float* W_z2p               = (const float*)d_in[18];
    const float* W_cq                = (const float*)d_in[19];
    const float* W_ck                = (const float*)d_in[20];
    const float* W_m1                = (const float*)d_in[21];
    const float* W_m2                = (const float*)d_in[22];
    const float* W_m3                = (const float*)d_in[23];
    float* out = (float*)d_out;

    prep_kernel<<<64, 256>>>(W_feat, W_s2c, W_z2p, ln_z_g, ln_z_b);
    tok_kernel<<<(Bc * Nc * 32) / 256, 256>>>(atom_to_token);
    s2c_kernel<<<Bc * Tc, 128>>>(s_trunk, ln_s_g, ln_s_b);
    c_kernel<<<(Bc * Nc) / 8, 256>>>(ref_pos, ref_charge, atom_pad_mask,
                                     ref_element, ref_atom_name_chars, W_cq, W_ck);
    z2pc_kernel<<<Bc * Tc, 256>>>(z);
    main_kernel<<<(Bc * 128 * 32 * 128) / 256, 256>>>(ref_pos, atom_pad_mask, ref_space_uid, z,
                                                      W_pos, W_dist, W_maskp,
                                                      W_m1, W_m2, W_m3, out);
}

// round 6
// speedup vs baseline: 2.1623x; 1.1724x over previous
#include <cuda_runtime.h>
#include <cstdint>

#define Bc 2
#define Nc 4096
#define Tc 512
#define CAP 64

// ---------------- scratch (static device globals; no allocation) ----------------
__device__ float  g_s2c[Bc * Tc * 128];                 // s_to_c
__device__ int    g_tok[Bc * Nc];                       // token index per atom
__device__ float  g_cq[Bc * Nc * 16];                   // relu(c) @ W_cq.T
__device__ float  g_ck[Bc * Nc * 16];                   // relu(c) @ W_ck.T
__device__ float  g_z2pc[(size_t)Bc * Tc * CAP * 16];   // compact z2p window (4 MB)
__device__ int    g_lo[Bc * Tc];                        // key-token window start per (b,tq)
__device__ int    g_amin[Bc * Tc];
__device__ int    g_amax[Bc * Tc];
__device__ int    g_anyovf;                             // any (b,tq) window exceeded CAP?
__device__ float4 g_WfD4[196 * 128];                    // (w[2f2][ch],w,w[2f2+1][ch],w) dup pairs
__device__ float  g_Ws2cT[384 * 128];
__device__ float  g_gw[16 * 128];                       // W_z2p * ln_z_g (folded)
__device__ float  g_gsum[16];
__device__ float  g_bw[16];

// ---------------- f32x2 / bf16 helpers ----------------
__device__ __forceinline__ void fma2(unsigned long long& acc, unsigned long long a, unsigned long long b) {
    asm("fma.rn.f32x2 %0, %1, %2, %0;" : "+l"(acc) : "l"(a), "l"(b));
}
__device__ __forceinline__ float lo32(unsigned long long v) { return __uint_as_float((unsigned)(v & 0xffffffffu)); }
__device__ __forceinline__ float hi32(unsigned long long v) { return __uint_as_float((unsigned)(v >> 32)); }
__device__ __forceinline__ unsigned pkbf(float lo, float hi) {
    unsigned r;
    asm("cvt.rn.bf16x2.f32 %0, %1, %2;" : "=r"(r) : "f"(hi), "f"(lo));
    return r;
}
__device__ __forceinline__ void mma16816(float* d, unsigned a0, unsigned a1, unsigned a2, unsigned a3,
                                         unsigned b0, unsigned b1) {
    asm("mma.sync.aligned.m16n8k16.row.col.f32.bf16.bf16.f32 "
        "{%0,%1,%2,%3}, {%4,%5,%6,%7}, {%8,%9}, {%10,%11,%12,%13};"
        : "=f"(d[0]), "=f"(d[1]), "=f"(d[2]), "=f"(d[3])
        : "r"(a0), "r"(a1), "r"(a2), "r"(a3), "r"(b0), "r"(b1),
          "f"(0.f), "f"(0.f), "f"(0.f), "f"(0.f));
}

// ---------------- prep: weight tables + layernorm fold + range/flag init ----------------
__global__ void prep_kernel(const float* __restrict__ W_feat, const float* __restrict__ W_s2c,
                            const float* __restrict__ W_z2p, const float* __restrict__ ln_z_g,
                            const float* __restrict__ ln_z_b) {
    int t = blockIdx.x * blockDim.x + threadIdx.x;
    int nt = gridDim.x * blockDim.x;
    for (int i = t; i < 196 * 128; i += nt) {
        int f2 = i >> 7, ch = i & 127;
        int fi0 = 2 * f2, fi1 = fi0 + 1;
        float w0 = (fi0 < 389) ? W_feat[ch * 389 + fi0] : 0.f;
        float w1 = (fi1 < 389) ? W_feat[ch * 389 + fi1] : 0.f;
        g_WfD4[i] = make_float4(w0, w0, w1, w1);
    }
    for (int i = t; i < 384 * 128; i += nt) {
        int ch = i / 384, f = i % 384;
        g_Ws2cT[f * 128 + ch] = W_s2c[i];
    }
    for (int i = t; i < 16 * 128; i += nt) {
        g_gw[i] = W_z2p[i] * ln_z_g[i & 127];
    }
    for (int i = t; i < Bc * Tc; i += nt) { g_amin[i] = Nc; g_amax[i] = -1; }
    if (t == 0) g_anyovf = 0;
    if (t < 16) {
        float gs = 0.f, bw = 0.f;
        for (int f = 0; f < 128; f++) {
            gs += W_z2p[t * 128 + f] * ln_z_g[f];
            bw += W_z2p[t * 128 + f] * ln_z_b[f];
        }
        g_gsum[t] = gs;
        g_bw[t] = bw;
    }
}

// ---------------- token index (one-hot argmax) + per-token atom range ----------------
__global__ void tok_kernel(const float* __restrict__ a2t) {
    int warp = (blockIdx.x * blockDim.x + threadIdx.x) >> 5;
    int lane = threadIdx.x & 31;
    if (warp >= Bc * Nc) return;
    const float4* row = (const float4*)(a2t + (size_t)warp * Tc);
    int idx = 0;
#pragma unroll
    for (int i = 0; i < 4; i++) {
        float4 v = row[lane + 32 * i];
        int base = 4 * (lane + 32 * i);
        if (v.x > 0.5f) idx = base;
        if (v.y > 0.5f) idx = base + 1;
        if (v.z > 0.5f) idx = base + 2;
        if (v.w > 0.5f) idx = base + 3;
    }
#pragma unroll
    for (int o = 16; o; o >>= 1) idx = max(idx, __shfl_xor_sync(0xffffffffu, idx, o));
    if (lane == 0) {
        g_tok[warp] = idx;
        int b = warp >> 12;
        int al = warp & (Nc - 1);
        atomicMin(&g_amin[b * Tc + idx], al);
        atomicMax(&g_amax[b * Tc + idx], al);
    }
}

// ---------------- s_to_c: layernorm(s_trunk) @ W_s2c.T ----------------
__global__ void s2c_kernel(const float* __restrict__ s_trunk, const float* __restrict__ g,
                           const float* __restrict__ bta) {
    __shared__ __align__(16) float xs[384];
    __shared__ float red[8];
    int row = blockIdx.x;
    int tid = threadIdx.x;
    const float* x = s_trunk + (size_t)row * 384;
    float v0 = x[tid], v1 = x[tid + 128], v2 = x[tid + 256];
    float s = v0 + v1 + v2, s2 = v0 * v0 + v1 * v1 + v2 * v2;
#pragma unroll
    for (int o = 16; o; o >>= 1) {
        s += __shfl_xor_sync(0xffffffffu, s, o);
        s2 += __shfl_xor_sync(0xffffffffu, s2, o);
    }
    if ((tid & 31) == 0) { red[tid >> 5] = s; red[4 + (tid >> 5)] = s2; }
    __syncthreads();
    s = red[0] + red[1] + red[2] + red[3];
    s2 = red[4] + red[5] + red[6] + red[7];
    float mu = s * (1.f / 384.f);
    float var = s2 * (1.f / 384.f) - mu * mu;
    float rs = rsqrtf(var + 1e-5f);
    xs[tid]       = (v0 - mu) * rs * g[tid]       + bta[tid];
    xs[tid + 128] = (v1 - mu) * rs * g[tid + 128] + bta[tid + 128];
    xs[tid + 256] = (v2 - mu) * rs * g[tid + 256] + bta[tid + 256];
    __syncthreads();
    float acc = 0.f;
#pragma unroll 4
    for (int f = 0; f < 384; f++) acc += xs[f] * g_Ws2cT[f * 128 + tid];
    g_s2c[(size_t)row * 128 + tid] = acc;
}

// ---- c embedding + cq/ck heads: 16 atoms/block, atom-pair f32x2, dup weights ----
__global__ void __launch_bounds__(256) c_kernel(
        const float* __restrict__ ref_pos, const float* __restrict__ ref_charge,
        const float* __restrict__ amask, const float* __restrict__ elem,
        const float* __restrict__ chars,
        const float* __restrict__ W_cq, const float* __restrict__ W_ck) {
    __shared__ __align__(16) float fs[392 * 20];   // [fi][atom 0..15 + pad4]; phase2 overlay
    __shared__ int ts[16];
    int tid = threadIdx.x;
    int abase = blockIdx.x * 16;

#pragma unroll
    for (int pass = 0; pass < 2; pass++) {
        int fi = tid + pass * 256;
        if (fi < 392) {
            float* row = fs + fi * 20;
#pragma unroll 4
            for (int a = 0; a < 16; a++) {
                int atom = abase + a;
                float v;
                if (fi < 3)        v = ref_pos[atom * 3 + fi];
                else if (fi == 3)  v = ref_charge[atom];
                else if (fi == 4)  v = amask[atom];
                else if (fi < 133) v = elem[(size_t)atom * 128 + (fi - 5)];
                else if (fi < 389) v = chars[(size_t)atom * 256 + (fi - 133)];
                else               v = 0.f;
                row[a] = v;
            }
        }
    }
    if (tid < 16) ts[tid] = g_tok[abase + tid];
    __syncthreads();

    int ch = tid & 127;
    int half = tid >> 7;                   // 0: atoms 0..7, 1: atoms 8..15
    const ulonglong2* wp = (const ulonglong2*)g_WfD4 + ch;
    const char* fb = (const char*)fs + half * 32;
    unsigned long long acc0 = 0, acc1 = 0, acc2 = 0, acc3 = 0;
#pragma unroll 4
    for (int f2 = 0; f2 < 196; f2++) {
        ulonglong2 ww = wp[(size_t)f2 * 128];           // dup weights fi=2f2 (.x), 2f2+1 (.y)
        const char* r0 = fb + (size_t)(2 * f2) * 80;
        ulonglong2 fa = *(const ulonglong2*)(r0);       // atom pairs (0,1),(2,3) of half
        ulonglong2 fbv = *(const ulonglong2*)(r0 + 16); // atom pairs (4,5),(6,7)
        ulonglong2 fc = *(const ulonglong2*)(r0 + 80);  // next fi row
        ulonglong2 fd = *(const ulonglong2*)(r0 + 96);
        fma2(acc0, fa.x, ww.x);  fma2(acc1, fa.y, ww.x);
        fma2(acc2, fbv.x, ww.x); fma2(acc3, fbv.y, ww.x);
        fma2(acc0, fc.x, ww.y);  fma2(acc1, fc.y, ww.y);
        fma2(acc2, fd.x, ww.y);  fma2(acc3, fd.y, ww.y);
    }

    int bb = abase >> 12;
    const float* srow = g_s2c + (size_t)bb * Tc * 128 + ch;
    unsigned long long aa[4] = { acc0, acc1, acc2, acc3 };
    float cv[8];
#pragma unroll
    for (int l = 0; l < 4; l++) {
        int a0 = half * 8 + 2 * l;
        cv[2 * l]     = fmaxf(lo32(aa[l]) + srow[(size_t)ts[a0] * 128], 0.f);
        cv[2 * l + 1] = fmaxf(hi32(aa[l]) + srow[(size_t)ts[a0 + 1] * 128], 0.f);
    }
    __syncthreads();                       // done reading fs

    float* cs  = fs;                        // [16][128]
    float* wcs = fs + 2048;                 // [2][16][130]
#pragma unroll
    for (int l = 0; l < 4; l++) {
        int a0 = half * 8 + 2 * l;
        cs[a0 * 128 + ch]       = cv[2 * l];
        cs[(a0 + 1) * 128 + ch] = cv[2 * l + 1];
    }
    for (int idx = tid; idx < 2 * 16 * 128; idx += 256) {
        int which = idx >> 11, i = (idx >> 7) & 15, chh = idx & 127;
        wcs[(which * 16 + i) * 130 + chh] = which ? W_ck[i * 128 + chh] : W_cq[i * 128 + chh];
    }
    __syncthreads();

    int i = tid & 15, which = (tid >> 4) & 1, a0 = tid >> 5;    // a0 in 0..7
    const unsigned long long* wr  = (const unsigned long long*)(wcs + (which * 16 + i) * 130);
    const unsigned long long* cr0 = (const unsigned long long*)(cs + a0 * 128);
    const unsigned long long* cr1 = (const unsigned long long*)(cs + (a0 + 8) * 128);
    unsigned long long s0 = 0, s1 = 0;
#pragma unroll 16
    for (int t2 = 0; t2 < 64; t2++) {
        unsigned long long w = wr[t2];
        fma2(s0, cr0[t2], w);
        fma2(s1, cr1[t2], w);
    }
    float* dst = which ? g_ck : g_cq;
    dst[(size_t)(abase + a0) * 16 + i]     = lo32(s0) + hi32(s0);
    dst[(size_t)(abase + a0 + 8) * 16 + i] = lo32(s1) + hi32(s1);
}

// ---------------- compact z_to_p: one block per (b,tq); computes lo + overflow flag ----
__global__ void z2pc_kernel(const float* __restrict__ z) {
    __shared__ __align__(16) float xs[64 * 132];
    __shared__ __align__(16) float gws[16 * 130];
    __shared__ float mus[64], rss[64], gsum_s[16], bw_s[16];
    __shared__ int lo_s;
    int tid = threadIdx.x;
    int bt = blockIdx.x;                 // b*Tc + tq

    if (tid == 0) {
        int lo = 0;
        int amx = g_amax[bt];
        if (amx >= 0) {
            int amn = g_amin[bt];
            int alo = 32 * (amn >> 5) - 48; if (alo < 0) alo = 0;
            int ahi = 32 * (amx >> 5) + 79; if (ahi > Nc - 1) ahi = Nc - 1;
            int bO = (bt >> 9) * Nc;
            lo = g_tok[bO + alo];
            int hi = g_tok[bO + ahi];
            if (hi - lo >= CAP) g_anyovf = 1;
        }
        g_lo[bt] = lo;
        lo_s = lo;
    }
    for (int i = tid; i < 2048; i += 256)
        gws[(i >> 7) * 130 + (i & 127)] = g_gw[i];
    if (tid < 16) { gsum_s[tid] = g_gsum[tid]; bw_s[tid] = g_bw[tid]; }
    __syncthreads();
    int lo = lo_s;

    {
        int r = tid >> 2, j = tid & 3;
        int tk = lo + r;
        if (tk > Tc - 1) tk = Tc - 1;
        const float4* src = (const float4*)(z + ((size_t)bt * Tc + tk) * 128) + j * 8;
        float4* dst = (float4*)(xs + r * 132) + j * 8;
        float s = 0.f, s2 = 0.f;
#pragma unroll
        for (int q = 0; q < 8; q++) {
            float4 t = src[q];
            dst[q] = t;
            s += (t.x + t.y) + (t.z + t.w);
            s2 += t.x * t.x + t.y * t.y + t.z * t.z + t.w * t.w;
        }
        s  += __shfl_xor_sync(0xffffffffu, s, 1);
        s2 += __shfl_xor_sync(0xffffffffu, s2, 1);
        s  += __shfl_xor_sync(0xffffffffu, s, 2);
        s2 += __shfl_xor_sync(0xffffffffu, s2, 2);
        if (j == 0) {
            float mu = s * (1.f / 128.f);
            float var = s2 * (1.f / 128.f) - mu * mu;
            mus[r] = mu;
            rss[r] = rsqrtf(var + 1e-5f);
        }
    }
    __syncthreads();

    int ch = tid & 15, rb = tid >> 4;
    const unsigned long long* wp = (const unsigned long long*)(gws + ch * 130);
    const unsigned long long* x0 = (const unsigned long long*)(xs + (rb * 4 + 0) * 132);
    const unsigned long long* x1 = (const unsigned long long*)(xs + (rb * 4 + 1) * 132);
    const unsigned long long* x2 = (const unsigned long long*)(xs + (rb * 4 + 2) * 132);
    const unsigned long long* x3 = (const unsigned long long*)(xs + (rb * 4 + 3) * 132);
    unsigned long long a0 = 0, a1 = 0, a2 = 0, a3 = 0;
#pragma unroll 16
    for (int f2 = 0; f2 < 64; f2++) {
        unsigned long long w = wp[f2];
        fma2(a0, x0[f2], w);
        fma2(a1, x1[f2], w);
        fma2(a2, x2[f2], w);
        fma2(a3, x3[f2], w);
    }
    float gs = gsum_s[ch], bw = bw_s[ch];
    float dots[4] = { lo32(a0) + hi32(a0), lo32(a1) + hi32(a1),
                      lo32(a2) + hi32(a2), lo32(a3) + hi32(a3) };
#pragma unroll
    for (int i = 0; i < 4; i++) {
        int r = rb * 4 + i;
        g_z2pc[((size_t)bt * CAP + r) * 16 + ch] = rss[r] * (dots[i] - mus[r] * gs) + bw;
    }
}

// ---------------- main: 1 position per thread; MLP via warp mma; NO fallback calls ----
__global__ void __launch_bounds__(256) main_kernel(
        const float* __restrict__ ref_pos, const float* __restrict__ amask,
        const int* __restrict__ uid,
        const float* __restrict__ W_pos, const float* __restrict__ W_dist,
        const float* __restrict__ W_maskp,
        const float* __restrict__ W_m1, const float* __restrict__ W_m2,
        const float* __restrict__ W_m3,
        float* __restrict__ out) {
    __shared__ float wpos[48], wdist[16], wmk[16];
    __shared__ __align__(16) float msm[8 * 640];   // per warp: 32 rows x 20 floats
    int tid = threadIdx.x;
    int lane = tid & 31, wid = tid >> 5;
    int g = lane >> 2, t = lane & 3;
    if (tid < 48) wpos[tid] = W_pos[tid];
    if (tid < 16) { wdist[tid] = W_dist[tid]; wmk[tid] = W_maskp[tid]; }

    unsigned bf[3][4];
#pragma unroll
    for (int L = 0; L < 3; L++) {
        const float* W = (L == 0) ? W_m1 : (L == 1) ? W_m2 : W_m3;
        float2 w00 = *(const float2*)(W + g * 16 + 2 * t);
        float2 w01 = *(const float2*)(W + g * 16 + 2 * t + 8);
        float2 w10 = *(const float2*)(W + (g + 8) * 16 + 2 * t);
        float2 w11 = *(const float2*)(W + (g + 8) * 16 + 2 * t + 8);
        bf[L][0] = pkbf(w00.x, w00.y);
        bf[L][1] = pkbf(w01.x, w01.y);
        bf[L][2] = pkbf(w10.x, w10.y);
        bf[L][3] = pkbf(w11.x, w11.y);
    }
    __syncthreads();

    int gidx = blockIdx.x * 256 + tid;
    int hh = gidx & 127;
    int ww = (gidx >> 7) & 31;
    int kk = (gidx >> 12) & 127;
    int b  = gidx >> 19;
    int q = kk * 32 + ww;
    int bq = b * Nc + q;
    int key = kk * 32 + hh - 48;
    bool inr = (unsigned)key < (unsigned)Nc;
    int bk = b * Nc + (inr ? key : 0);

    float mq = amask[bq];
    float mk = inr ? amask[bk] : 0.f;
    int uq = uid[bq];
    int uk = uid[bk];
    float v = (mq != 0.f && mk != 0.f && uq == uk) ? 1.f : 0.f;

    float qx = ref_pos[bq * 3], qy = ref_pos[bq * 3 + 1], qz = ref_pos[bq * 3 + 2];
    float kx = 0.f, ky = 0.f, kz = 0.f;
    if (inr) { kx = ref_pos[bk * 3]; ky = ref_pos[bk * 3 + 1]; kz = ref_pos[bk * 3 + 2]; }
    float dx = kx - qx, dy = ky - qy, dz = kz - qz;
    float dn = 1.f / (1.f + dx * dx + dy * dy + dz * dz);

    float p[16];
#pragma unroll
    for (int d = 0; d < 16; d++)
        p[d] = v * (dx * wpos[3 * d] + dy * wpos[3 * d + 1] + dz * wpos[3 * d + 2]
                    + dn * wdist[d] + wmk[d]);
    {
        const float4* cq4 = (const float4*)(g_cq + (size_t)bq * 16);
#pragma unroll
        for (int i = 0; i < 4; i++) {
            float4 tt = cq4[i];
            p[4 * i] += tt.x; p[4 * i + 1] += tt.y; p[4 * i + 2] += tt.z; p[4 * i + 3] += tt.w;
        }
    }
    if (inr) {
        int tq = g_tok[bq];
        int lo = g_lo[b * Tc + tq];
        int j = g_tok[bk] - lo;
        if (j >= CAP) j = CAP - 1;   // overflow handled exactly by fixup_kernel
        const float4* zp4 = (const float4*)(g_z2pc + (((size_t)(b * Tc + tq)) * CAP + j) * 16);
        const float4* ck4 = (const float4*)(g_ck + (size_t)bk * 16);
#pragma unroll
        for (int i = 0; i < 4; i++) {
            float4 tt = zp4[i], u = ck4[i];
            p[4 * i]     += tt.x + u.x;
            p[4 * i + 1] += tt.y + u.y;
            p[4 * i + 2] += tt.z + u.z;
            p[4 * i + 3] += tt.w + u.w;
        }
    }

    float* wsm = msm + wid * 640;
    unsigned* h2 = (unsigned*)wsm;
#pragma unroll
    for (int j2 = 0; j2 < 8; j2++)
        h2[lane * 10 + j2] = pkbf(fmaxf(p[2 * j2], 0.f), fmaxf(p[2 * j2 + 1], 0.f));
    __syncwarp();

    unsigned a0[2], a1[2], a2[2], a3[2];
#pragma unroll
    for (int tt = 0; tt < 2; tt++) {
        int rt = tt * 16;
        a0[tt] = h2[(rt + g) * 10 + t];
        a1[tt] = h2[(rt + g + 8) * 10 + t];
        a2[tt] = h2[(rt + g) * 10 + t + 4];
        a3[tt] = h2[(rt + g + 8) * 10 + t + 4];
    }
    __syncwarp();

#pragma unroll
    for (int tt = 0; tt < 2; tt++) {
        unsigned u0 = a0[tt], u1 = a1[tt], u2 = a2[tt], u3 = a3[tt];
        float dlo[4], dhi[4];
#pragma unroll
        for (int L = 0; L < 3; L++) {
            mma16816(dlo, u0, u1, u2, u3, bf[L][0], bf[L][1]);
            mma16816(dhi, u0, u1, u2, u3, bf[L][2], bf[L][3]);
            if (L < 2) {
                u0 = pkbf(fmaxf(dlo[0], 0.f), fmaxf(dlo[1], 0.f));
                u1 = pkbf(fmaxf(dlo[2], 0.f), fmaxf(dlo[3], 0.f));
                u2 = pkbf(fmaxf(dhi[0], 0.f), fmaxf(dhi[1], 0.f));
                u3 = pkbf(fmaxf(dhi[2], 0.f), fmaxf(dhi[3], 0.f));
            }
        }
        int r0 = tt * 16 + g, r1 = r0 + 8;
        *(float2*)(wsm + r0 * 20 + 2 * t)     = make_float2(dlo[0], dlo[1]);
        *(float2*)(wsm + r1 * 20 + 2 * t)     = make_float2(dlo[2], dlo[3]);
        *(float2*)(wsm + r0 * 20 + 8 + 2 * t) = make_float2(dhi[0], dhi[1]);
        *(float2*)(wsm + r1 * 20 + 8 + 2 * t) = make_float2(dhi[2], dhi[3]);
    }
    __syncwarp();

    float4* o4 = (float4*)(out + (size_t)gidx * 16);
    const float4* mrow = (const float4*)(wsm + lane * 20);
#pragma unroll
    for (int i = 0; i < 4; i++) {
        float4 mi = mrow[i];
        o4[i] = make_float4(p[4 * i] + mi.x, p[4 * i + 1] + mi.y,
                            p[4 * i + 2] + mi.z, p[4 * i + 3] + mi.w);
    }
}

// ---------------- fixup: exact recompute of window-overflow positions (rare) ----------
__global__ void fixup_kernel(
        const float* __restrict__ ref_pos, const float* __restrict__ amask,
        const int* __restrict__ uid, const float* __restrict__ z,
        const float* __restrict__ W_pos, const float* __restrict__ W_dist,
        const float* __restrict__ W_maskp,
        const float* __restrict__ W_m1, const float* __restrict__ W_m2,
        const float* __restrict__ W_m3,
        float* __restrict__ out) {
    if (!g_anyovf) return;
    int bt = blockIdx.x;                  // b*Tc + tq
    int amx = g_amax[bt];
    if (amx < 0) return;
    int amn = g_amin[bt];
    int b = bt >> 9;
    int alo = 32 * (amn >> 5) - 48; if (alo < 0) alo = 0;
    int ahi = 32 * (amx >> 5) + 79; if (ahi > Nc - 1) ahi = Nc - 1;
    int lo = g_tok[b * Nc + alo];
    int hi = g_tok[b * Nc + ahi];
    if (hi - lo < CAP) return;            // this tq was fully handled by main

    int hh = threadIdx.x;                 // 128 threads
    for (int q = amn; q <= amx; q++) {
        int kk = q >> 5;
        int key = kk * 32 + hh - 48;
        if ((unsigned)key >= (unsigned)Nc) continue;
        int bq = b * Nc + q;
        int bk = b * Nc + key;
        int tk2 = g_tok[bk];
        if (tk2 - lo < CAP) continue;     // main's value exact

        float mq = amask[bq], mk = amask[bk];
        float vv = (mq != 0.f && mk != 0.f && uid[bq] == uid[bk]) ? 1.f : 0.f;
        float dx = ref_pos[bk * 3] - ref_pos[bq * 3];
        float dy = ref_pos[bk * 3 + 1] - ref_pos[bq * 3 + 1];
        float dz = ref_pos[bk * 3 + 2] - ref_pos[bq * 3 + 2];
        float dn = 1.f / (1.f + dx * dx + dy * dy + dz * dz);

        // exact z2p for (bt, tk2)
        const float* zrow = z + ((size_t)bt * Tc + tk2) * 128;
        float s = 0.f, s2 = 0.f;
        for (int f = 0; f < 128; f++) { float x = zrow[f]; s += x; s2 += x * x; }
        float mu = s * (1.f / 128.f);
        float rs = rsqrtf(s2 * (1.f / 128.f) - mu * mu + 1e-5f);

        float p[16];
        for (int d = 0; d < 16; d++) {
            float dot = 0.f;
            for (int f = 0; f < 128; f++) dot += zrow[f] * g_gw[d * 128 + f];
            float zc = rs * (dot - mu * g_gsum[d]) + g_bw[d];
            p[d] = vv * (dx * W_pos[3 * d] + dy * W_pos[3 * d + 1] + dz * W_pos[3 * d + 2]
                         + dn * W_dist[d] + W_maskp[d])
                   + g_cq[(size_t)bq * 16 + d] + g_ck[(size_t)bk * 16 + d] + zc;
        }
        float r0[16], r1[16], r2[16], m[16];
        for (int i = 0; i < 16; i++) {
            float a = 0.f;
            for (int j = 0; j < 16; j++) a += fmaxf(p[j], 0.f) * W_m1[i * 16 + j];
            r0[i] = a;
        }
        for (int i = 0; i < 16; i++) {
            float a = 0.f;
            for (int j = 0; j < 16; j++) a += fmaxf(r0[j], 0.f) * W_m2[i * 16 + j];
            r1[i] = a;
        }
        for (int i = 0; i < 16; i++) {
            float a = 0.f;
            for (int j = 0; j < 16; j++) a += fmaxf(r1[j], 0.f) * W_m3[i * 16 + j];
            r2[i] = a;
        }
        for (int i = 0; i < 16; i++) m[i] = p[i] + r2[i];
        size_t gidx = ((size_t)b << 19) | ((size_t)kk << 12) | ((size_t)(q & 31) << 7) | hh;
        float* o = out + gidx * 16;
        for (int i = 0; i < 16; i++) o[i] = m[i];
    }
}

// ---------------- launch ----------------
extern "C" void kernel_launch(void* const* d_in, const int* in_sizes, int n_in,
                              void* d_out, int out_size) {
    const float* ref_pos             = (const float*)d_in[0];
    const float* ref_charge          = (const float*)d_in[1];
    const float* atom_pad_mask       = (const float*)d_in[2];
    const float* ref_element         = (const float*)d_in[3];
    const float* ref_atom_name_chars = (const float*)d_in[4];
    const int*   ref_space_uid       = (const int*)  d_in[5];
    const float* atom_to_token       = (const float*)d_in[6];
    const float* s_trunk             = (const float*)d_in[7];
    const float* z                   = (const float*)d_in[8];
    const float* W_feat              = (const float*)d_in[9];
    const float* W_pos               = (const float*)d_in[10];
    const float* W_dist              = (const float*)d_in[11];
    const float* W_maskp             = (const float*)d_in[12];
    const float* ln_s_g              = (const float*)d_in[13];
    const float* ln_s_b              = (const float*)d_in[14];
    const float* W_s2c               = (const float*)d_in[15];
    const float* ln_z_g              = (const float*)d_in[16];
    const float* ln_z_b              = (const float*)d_in[17];
    const float* W_z2p               = (const float*)d_in[18];
    const float* W_cq                = (const float*)d_in[19];
    const float* W_ck                = (const float*)d_in[20];
    const float* W_m1                = (const float*)d_in[21];
    const float* W_m2                = (const float*)d_in[22];
    const float* W_m3                = (const float*)d_in[23];
    float* out = (float*)d_out;

    prep_kernel<<<64, 256>>>(W_feat, W_s2c, W_z2p, ln_z_g, ln_z_b);
    tok_kernel<<<(Bc * Nc * 32) / 256, 256>>>(atom_to_token);
    s2c_kernel<<<Bc * Tc, 128>>>(s_trunk, ln_s_g, ln_s_b);
    c_kernel<<<(Bc * Nc) / 16, 256>>>(ref_pos, ref_charge, atom_pad_mask,
                                      ref_element, ref_atom_name_chars, W_cq, W_ck);
    z2pc_kernel<<<Bc * Tc, 256>>>(z);
    main_kernel<<<(Bc * 128 * 32 * 128) / 256, 256>>>(ref_pos, atom_pad_mask, ref_space_uid,
                                                      W_pos, W_dist, W_maskp,
                                                      W_m1, W_m2, W_m3, out);
    fixup_kernel<<<Bc * Tc, 128>>>(ref_pos, atom_pad_mask, ref_space_uid, z,
                                   W_pos, W_dist, W_maskp, W_m1, W_m2, W_m3, out);
}